// round 6
// baseline (speedup 1.0000x reference)
#include <cuda_runtime.h>
#include <math.h>

#define TT  50
#define BB  1024
#define BEL 200
#define ST  30
#define ACT 8
#define EMB 1024

static const size_t OFF_B  = 0;
static const size_t OFF_PS = (size_t)TT * BB * BEL;
static const size_t SZ30   = (size_t)TT * BB * ST;
static const size_t OFF_MP = OFF_PS + SZ30;
static const size_t OFF_SP = OFF_MP + SZ30;
static const size_t OFF_PO = OFF_SP + SZ30;
static const size_t OFF_MQ = OFF_PO + SZ30;
static const size_t OFF_SQ = OFF_MQ + SZ30;

__device__ __align__(16) float g_obs[(size_t)TT * BB * BEL];
// packed weights (all [k4][colgroup][4cols][4k] except Wsa: [k4][j][4k])
__device__ __align__(16) float g_Wsa[8000];     // K padded 38->40, 10 k4 x 200
__device__ __align__(16) float g_Wg4[240000];   // 50 k4 x 300 cg (cg<150: gi, else gh)
__device__ __align__(16) float g_Wh4[80000];    // 50 k4 x 100 cg (col<200: Wbp, else Wbq_b)
__device__ __align__(16) float g_Wo4[24000];    // 50 k4 x 30 cg (col<60: Wsp, else Wsq)

typedef unsigned long long u64;

__device__ __forceinline__ void ffma2(u64& acc, u64 a, u64 b) {
    asm("fma.rn.f32x2 %0, %1, %2, %0;" : "+l"(acc) : "l"(a), "l"(b));
}
__device__ __forceinline__ float hsum2(u64 v) {
    float lo, hi;
    asm("mov.b64 {%0,%1}, %2;" : "=f"(lo), "=f"(hi) : "l"(v));
    return lo + hi;
}
__device__ __forceinline__ float sigm(float x) { return 1.f / (1.f + __expf(-x)); }
__device__ __forceinline__ float tanhfast(float x) { return 1.f - 2.f / (__expf(2.f * x) + 1.f); }
__device__ __forceinline__ float softplusf(float x) {
    return fmaxf(x, 0.f) + log1pf(__expf(-fabsf(x)));
}

// ---------------------------------------------------------------------------
#define PREP_N 352000
__global__ void k_prep(const float* __restrict__ W_sa, const float* __restrict__ W_ih,
                       const float* __restrict__ W_hh, const float* __restrict__ W_bp,
                       const float* __restrict__ W_sp, const float* __restrict__ W_bq,
                       const float* __restrict__ W_sq) {
    int idx = blockIdx.x * blockDim.x + threadIdx.x;
    if (idx >= PREP_N) return;
    if (idx < 8000) {                       // g_Wsa: [k4][j][4]
        int k4 = idx / 800, r = idx % 800, j = r >> 2, k = 4 * k4 + (r & 3);
        g_Wsa[idx] = (k < 38) ? W_sa[j * 38 + k] : 0.f;   // k<30: state, 30..38: action
        return;
    }
    if (idx < 248000) {                     // g_Wg4
        int l = idx - 8000, k4 = l / 4800, r = l % 4800;
        int cg = r >> 4, c = (r >> 2) & 3, k = 4 * k4 + (r & 3);
        g_Wg4[l] = (cg < 150) ? W_ih[(4 * cg + c) * 200 + k]
                              : W_hh[(4 * (cg - 150) + c) * 200 + k];
        return;
    }
    if (idx < 328000) {                     // g_Wh4
        int l = idx - 248000, k4 = l / 1600, r = l % 1600;
        int cg = r >> 4, c = (r >> 2) & 3, k = 4 * k4 + (r & 3);
        int col = 4 * cg + c;
        g_Wh4[l] = (col < 200) ? W_bp[col * 200 + k]
                               : W_bq[(size_t)(col - 200) * 1224 + k];
        return;
    }
    {                                       // g_Wo4
        int l = idx - 328000, k4 = l / 480, r = l % 480;
        int cg = r >> 4, c = (r >> 2) & 3, k = 4 * k4 + (r & 3);
        int col = 4 * cg + c;
        g_Wo4[l] = (col < 60) ? W_sp[col * 200 + k] : W_sq[(col - 60) * 200 + k];
    }
}

// ---------------------------------------------------------------------------
// Obs GEMM (unchanged, proven): g_obs = obs @ Wbq_e^T + b_bq
// ---------------------------------------------------------------------------
__global__ __launch_bounds__(320, 1) void k_obs_gemm(const float* __restrict__ A,
                                                     const float* __restrict__ W_bq,
                                                     const float* __restrict__ b_bq) {
    __shared__ __align__(16) float As[2][64 * 20];
    __shared__ __align__(16) float Bs[2][200 * 18];
    const int tid = threadIdx.x;
    const size_t row0 = (size_t)blockIdx.x * 64;
    const int r0 = (tid / 20) * 4, c0 = (tid % 20) * 10;
    u64 acc[4][10];
#pragma unroll
    for (int i = 0; i < 4; i++)
#pragma unroll
        for (int j = 0; j < 10; j++) acc[i][j] = 0ULL;
    const int arow = tid >> 2, ak4 = tid & 3;
    if (tid < 256)
        *(float4*)&As[0][arow * 20 + ak4 * 4] = *(const float4*)&A[(row0 + arow) * EMB + ak4 * 4];
    for (int idx = tid; idx < 800; idx += 320) {
        int col = idx >> 2, e4 = idx & 3;
        float4 v = *(const float4*)&W_bq[(size_t)col * 1224 + 200 + e4 * 4];
        Bs[0][col * 18 + e4 * 4 + 0] = v.x; Bs[0][col * 18 + e4 * 4 + 1] = v.y;
        Bs[0][col * 18 + e4 * 4 + 2] = v.z; Bs[0][col * 18 + e4 * 4 + 3] = v.w;
    }
    __syncthreads();
    for (int kti = 0; kti < 64; kti++) {
        const int cur = kti & 1;
        const bool hn = (kti + 1) < 64;
        float4 pa; float4 pb[3]; int nb = 0;
        if (hn) {
            int kt = (kti + 1) * 16;
            if (tid < 256) pa = *(const float4*)&A[(row0 + arow) * EMB + kt + ak4 * 4];
            for (int idx = tid; idx < 800; idx += 320) {
                int col = idx >> 2, e4 = idx & 3;
                pb[nb++] = *(const float4*)&W_bq[(size_t)col * 1224 + 200 + kt + e4 * 4];
            }
        }
#pragma unroll
        for (int kp = 0; kp < 8; kp++) {
            u64 a2[4], b2[10];
#pragma unroll
            for (int i = 0; i < 4; i++) a2[i] = *(const u64*)&As[cur][(r0 + i) * 20 + 2 * kp];
#pragma unroll
            for (int j = 0; j < 10; j++) b2[j] = *(const u64*)&Bs[cur][(c0 + j) * 18 + 2 * kp];
#pragma unroll
            for (int i = 0; i < 4; i++)
#pragma unroll
                for (int j = 0; j < 10; j++) ffma2(acc[i][j], a2[i], b2[j]);
        }
        if (hn) {
            int nxt = cur ^ 1;
            if (tid < 256) *(float4*)&As[nxt][arow * 20 + ak4 * 4] = pa;
            nb = 0;
            for (int idx = tid; idx < 800; idx += 320) {
                int col = idx >> 2, e4 = idx & 3;
                float4 v = pb[nb++];
                Bs[nxt][col * 18 + e4 * 4 + 0] = v.x; Bs[nxt][col * 18 + e4 * 4 + 1] = v.y;
                Bs[nxt][col * 18 + e4 * 4 + 2] = v.z; Bs[nxt][col * 18 + e4 * 4 + 3] = v.w;
            }
        }
        __syncthreads();
    }
#pragma unroll
    for (int i = 0; i < 4; i++)
#pragma unroll
        for (int j = 0; j < 10; j++)
            g_obs[(row0 + r0 + i) * BEL + c0 + j] = hsum2(acc[i][j]) + b_bq[c0 + j];
}

// ---------------------------------------------------------------------------
// Persistent scan, 128 blocks x 512 threads, 8 rows/block, B8xC4 register tiles.
// ---------------------------------------------------------------------------
#define SCAN_SMEM (21240 * 4)

__global__ __launch_bounds__(512, 1) void k_scan(
    const float* __restrict__ nonterm, const float* __restrict__ prev_state,
    const float* __restrict__ prev_belief, const float* __restrict__ actions,
    const float* __restrict__ noise_p, const float* __restrict__ noise_q,
    const float* __restrict__ b_sa, const float* __restrict__ b_ih,
    const float* __restrict__ b_hh, const float* __restrict__ b_bp,
    const float* __restrict__ b_sp, const float* __restrict__ b_sq,
    float* __restrict__ out) {
    extern __shared__ __align__(16) float sm[];
    float* s_sh = sm;            // 8x40 = 320
    float* hid  = sm + 320;      // 1600
    float* bel  = hid + 1600;    // 1600
    float* tmp  = bel + 1600;    // 12800 (PhB gates 9600 / PhD partials 12800 / PhE partials 9600)
    float* obs  = tmp + 12800;   // 1600
    float* hp   = obs + 1600;    // 1600
    float* hq   = hp + 1600;     // 1600
    float* bias = hq + 1600;     // 120    => 21240 floats

    const int tid = threadIdx.x;
    const int b0 = blockIdx.x * 8;

    float r_bsa = 0.f, r_bir = 0.f, r_biz = 0.f, r_bin = 0.f;
    float r_bhr = 0.f, r_bhz = 0.f, r_bhn = 0.f, r_bbp = 0.f;
    if (tid < 200) {
        r_bsa = b_sa[tid];
        r_bir = b_ih[tid]; r_biz = b_ih[200 + tid]; r_bin = b_ih[400 + tid];
        r_bhr = b_hh[tid]; r_bhz = b_hh[200 + tid]; r_bhn = b_hh[400 + tid];
        r_bbp = b_bp[tid];
    }
    if (tid < 120) bias[tid] = (tid < 60) ? b_sp[tid] : b_sq[tid - 60];

    for (int idx = tid; idx < 1600; idx += 512) {
        int bb = idx / 200, j = idx % 200;
        bel[idx] = prev_belief[(size_t)(b0 + bb) * BEL + j];
    }
    if (tid < 320) {
        int bb = tid / 40, c = tid % 40;
        float v = 0.f;
        if (c < 30)      v = prev_state[(size_t)(b0 + bb) * ST + c] * nonterm[b0 + bb];
        else if (c < 38) v = actions[(size_t)(b0 + bb) * ACT + (c - 30)];
        s_sh[tid] = v;
    }
    __syncthreads();

    for (int t = 0; t < TT; t++) {
        // ===== PhA: hidden = relu(s_a @ Wsa^T + b_sa); others stage obs =====
        if (tid < 200) {
            u64 acc[8];
#pragma unroll
            for (int r = 0; r < 8; r++) acc[r] = 0ULL;
#pragma unroll
            for (int k4 = 0; k4 < 10; k4++) {
                ulonglong2 w = __ldg((const ulonglong2*)&g_Wsa[(k4 * 200 + tid) * 4]);
#pragma unroll
                for (int r = 0; r < 8; r++) {
                    ulonglong2 s = *(const ulonglong2*)&s_sh[r * 40 + k4 * 4];
                    ffma2(acc[r], s.x, w.x);
                    ffma2(acc[r], s.y, w.y);
                }
            }
#pragma unroll
            for (int r = 0; r < 8; r++)
                hid[r * 200 + tid] = fmaxf(hsum2(acc[r]) + r_bsa, 0.f);
        } else {
            for (int i = tid - 200; i < 400; i += 312)
                *(float4*)&obs[i * 4] =
                    *(const float4*)&g_obs[((size_t)t * BB + b0) * BEL + i * 4];
        }
        __syncthreads();

        // ===== PhB: gates gi|gh. 300 threads, 4 cols x 8 rows each =====
        if (tid < 300) {
            const float* src = (tid < 150) ? hid : bel;
            const ulonglong2* wp = (const ulonglong2*)g_Wg4 + tid * 4;  // stride/k4 = 1200
            u64 acc[4][8];
#pragma unroll
            for (int c = 0; c < 4; c++)
#pragma unroll
                for (int r = 0; r < 8; r++) acc[c][r] = 0ULL;
            ulonglong2 w0[4], w1[4];
#pragma unroll
            for (int c = 0; c < 4; c++) { w0[c] = wp[c]; w1[c] = wp[1200 + c]; }
#pragma unroll 2
            for (int k4 = 0; k4 < 50; k4++) {
                ulonglong2 wc[4];
#pragma unroll
                for (int c = 0; c < 4; c++) { wc[c] = w0[c]; w0[c] = w1[c]; }
                if (k4 + 2 < 50) {
#pragma unroll
                    for (int c = 0; c < 4; c++) w1[c] = wp[(k4 + 2) * 1200 + c];
                }
#pragma unroll
                for (int r = 0; r < 8; r++) {
                    ulonglong2 h = *(const ulonglong2*)&src[r * 200 + k4 * 4];
#pragma unroll
                    for (int c = 0; c < 4; c++) {
                        ffma2(acc[c][r], h.x, wc[c].x);
                        ffma2(acc[c][r], h.y, wc[c].y);
                    }
                }
            }
            float* dst = tmp + ((tid < 150) ? 0 : 4800);
            const int c0 = 4 * ((tid < 150) ? tid : tid - 150);
#pragma unroll
            for (int r = 0; r < 8; r++) {
                float4 v = make_float4(hsum2(acc[0][r]), hsum2(acc[1][r]),
                                       hsum2(acc[2][r]), hsum2(acc[3][r]));
                *(float4*)&dst[r * 600 + c0] = v;
            }
        }
        __syncthreads();

        // ===== PhC: GRU combine -> new belief =====
        if (tid < 200) {
            const float* gh = tmp + 4800;
#pragma unroll
            for (int r = 0; r < 8; r++) {
                float rr = sigm(tmp[r * 600 + tid] + r_bir + gh[r * 600 + tid] + r_bhr);
                float z  = sigm(tmp[r * 600 + 200 + tid] + r_biz + gh[r * 600 + 200 + tid] + r_bhz);
                float n  = tanhfast(tmp[r * 600 + 400 + tid] + r_bin +
                                    rr * (gh[r * 600 + 400 + tid] + r_bhn));
                float nb = (1.f - z) * n + z * bel[r * 200 + tid];
                bel[r * 200 + tid] = nb;
                out[OFF_B + ((size_t)t * BB + b0 + r) * BEL + tid] = nb;
            }
        }
        __syncthreads();

        // ===== PhD: hp/hq pre-acts. 400 threads = 100 cg x 4 k-splits =====
        {
            const int cg = tid % 100, kh = tid / 100;     // valid tid<400
            const int kbeg = kh * 13 - ((kh >= 2) ? (kh - 2) : 0);
            const int kend = kbeg + 13 - ((kh >= 2) ? 1 : 0);
            if (tid < 400) {
                const ulonglong2* wp = (const ulonglong2*)g_Wh4 + cg * 4;  // stride/k4 = 400
                u64 acc[4][8];
#pragma unroll
                for (int c = 0; c < 4; c++)
#pragma unroll
                    for (int r = 0; r < 8; r++) acc[c][r] = 0ULL;
                ulonglong2 w0[4], w1[4];
#pragma unroll
                for (int c = 0; c < 4; c++) {
                    w0[c] = wp[kbeg * 400 + c];
                    w1[c] = wp[(kbeg + 1) * 400 + c];
                }
                for (int k4 = kbeg; k4 < kend; k4++) {
                    ulonglong2 wc[4];
#pragma unroll
                    for (int c = 0; c < 4; c++) { wc[c] = w0[c]; w0[c] = w1[c]; }
                    if (k4 + 2 < kend) {
#pragma unroll
                        for (int c = 0; c < 4; c++) w1[c] = wp[(k4 + 2) * 400 + c];
                    }
#pragma unroll
                    for (int r = 0; r < 8; r++) {
                        ulonglong2 h = *(const ulonglong2*)&bel[r * 200 + k4 * 4];
#pragma unroll
                        for (int c = 0; c < 4; c++) {
                            ffma2(acc[c][r], h.x, wc[c].x);
                            ffma2(acc[c][r], h.y, wc[c].y);
                        }
                    }
                }
#pragma unroll
                for (int r = 0; r < 8; r++) {
                    float4 v = make_float4(hsum2(acc[0][r]), hsum2(acc[1][r]),
                                           hsum2(acc[2][r]), hsum2(acc[3][r]));
                    *(float4*)&tmp[kh * 3200 + r * 400 + 4 * cg] = v;
                }
            }
        }
        __syncthreads();

        // ===== reduce 4 partials -> hp / hq (+relu) =====
        if (tid < 400) {
#pragma unroll
            for (int r = 0; r < 8; r++) {
                float v = tmp[r * 400 + tid] + tmp[3200 + r * 400 + tid] +
                          tmp[6400 + r * 400 + tid] + tmp[9600 + r * 400 + tid];
                if (tid < 200) hp[r * 200 + tid] = fmaxf(v + r_bbp, 0.f);
                else hq[r * 200 + tid - 200] = fmaxf(v + obs[r * 200 + tid - 200], 0.f);
            }
        }
        __syncthreads();

        // ===== PhE: head projections. 300 threads = 30 cg x 10 k-splits =====
        if (tid < 300) {
            const int cg = tid % 30, q = tid / 30;
            const float* src = (cg < 15) ? hp : hq;
            u64 acc[4][8];
#pragma unroll
            for (int c = 0; c < 4; c++)
#pragma unroll
                for (int r = 0; r < 8; r++) acc[c][r] = 0ULL;
#pragma unroll
            for (int kk = 0; kk < 5; kk++) {
                int k4 = q * 5 + kk;
                ulonglong2 wc[4];
#pragma unroll
                for (int c = 0; c < 4; c++)
                    wc[c] = __ldg((const ulonglong2*)g_Wo4 + k4 * 120 + cg * 4 + c);
#pragma unroll
                for (int r = 0; r < 8; r++) {
                    ulonglong2 h = *(const ulonglong2*)&src[r * 200 + k4 * 4];
#pragma unroll
                    for (int c = 0; c < 4; c++) {
                        ffma2(acc[c][r], h.x, wc[c].x);
                        ffma2(acc[c][r], h.y, wc[c].y);
                    }
                }
            }
#pragma unroll
            for (int r = 0; r < 8; r++) {
                float4 v = make_float4(hsum2(acc[0][r]), hsum2(acc[1][r]),
                                       hsum2(acc[2][r]), hsum2(acc[3][r]));
                *(float4*)&tmp[q * 960 + r * 120 + 4 * cg] = v;
            }
        }
        __syncthreads();

        // ===== PhF: reduce heads, sample, write outputs, next s_sh =====
        if (tid < 240) {
            const int bb = tid / 30, i = tid - bb * 30;
            size_t gidx = ((size_t)t * BB + b0 + bb) * ST + i;
            float np = noise_p[gidx], nq = noise_q[gidx];
            float mp = bias[i], spr = bias[30 + i], mq = bias[60 + i], sqr = bias[90 + i];
#pragma unroll
            for (int q = 0; q < 10; q++) {
                mp  += tmp[q * 960 + bb * 120 + i];
                spr += tmp[q * 960 + bb * 120 + 30 + i];
                mq  += tmp[q * 960 + bb * 120 + 60 + i];
                sqr += tmp[q * 960 + bb * 120 + 90 + i];
            }
            float spv = softplusf(spr) + 0.1f;
            float sqv = softplusf(sqr) + 0.1f;
            float po  = fmaf(sqv, nq, mq);
            out[OFF_MP + gidx] = mp;
            out[OFF_SP + gidx] = spv;
            out[OFF_PS + gidx] = fmaf(spv, np, mp);
            out[OFF_MQ + gidx] = mq;
            out[OFF_SQ + gidx] = sqv;
            out[OFF_PO + gidx] = po;
            if (t + 1 < TT)
                s_sh[bb * 40 + i] = po * nonterm[(size_t)(t + 1) * BB + b0 + bb];
        } else if (tid < 304) {
            int idx = tid - 240, bb = idx >> 3, i = idx & 7;
            if (t + 1 < TT)
                s_sh[bb * 40 + 30 + i] = actions[((size_t)(t + 1) * BB + b0 + bb) * ACT + i];
        }
        __syncthreads();
    }
}

// ---------------------------------------------------------------------------
extern "C" void kernel_launch(void* const* d_in, const int* in_sizes, int n_in,
                              void* d_out, int out_size) {
    const float* prev_state   = (const float*)d_in[0];
    const float* actions      = (const float*)d_in[1];
    const float* prev_belief  = (const float*)d_in[2];
    const float* observations = (const float*)d_in[3];
    const float* nonterm      = (const float*)d_in[4];
    const float* noise_p      = (const float*)d_in[5];
    const float* noise_q      = (const float*)d_in[6];
    const float* W_sa = (const float*)d_in[7];  const float* b_sa = (const float*)d_in[8];
    const float* W_ih = (const float*)d_in[9];  const float* b_ih = (const float*)d_in[10];
    const float* W_hh = (const float*)d_in[11]; const float* b_hh = (const float*)d_in[12];
    const float* W_bp = (const float*)d_in[13]; const float* b_bp = (const float*)d_in[14];
    const float* W_sp = (const float*)d_in[15]; const float* b_sp = (const float*)d_in[16];
    const float* W_bq = (const float*)d_in[17]; const float* b_bq = (const float*)d_in[18];
    const float* W_sq = (const float*)d_in[19]; const float* b_sq = (const float*)d_in[20];
    float* out = (float*)d_out;
    (void)in_sizes; (void)n_in; (void)out_size;

    static int done = 0;
    if (!done) {
        cudaFuncSetAttribute(k_scan, cudaFuncAttributeMaxDynamicSharedMemorySize, SCAN_SMEM);
        done = 1;
    }
    k_prep<<<(PREP_N + 255) / 256, 256>>>(W_sa, W_ih, W_hh, W_bp, W_sp, W_bq, W_sq);
    k_obs_gemm<<<(TT * BB) / 64, 320>>>(observations, W_bq, b_bq);
    k_scan<<<BB / 8, 512, SCAN_SMEM>>>(nonterm, prev_state, prev_belief, actions,
                                       noise_p, noise_q, b_sa, b_ih, b_hh,
                                       b_bp, b_sp, b_sq, out);
}